// round 15
// baseline (speedup 1.0000x reference)
#include <cuda_runtime.h>
#include <cuda_fp16.h>
#include <math.h>

// ---------------------------------------------------------------------------
// Problem constants
// ---------------------------------------------------------------------------
#define BATCH 2
#define SEQ   2048
#define CH    768
#define HEADS 24
#define HD    32
#define L_PER_B (SEQ * CH)
#define TOT (BATCH * SEQ * CH)

// fp32 scratch
__device__ float g_res[TOT];
// half scratch
__device__ __half g_xhi[TOT];
__device__ __half g_xlo[TOT];
__device__ __half g_qhi[TOT];
__device__ __half g_qlo[TOT];
__device__ __half g_vpT[TOT];     // [b][c][token]
__device__ __half g_vT[TOT];      // [b][c][token]
__device__ __half g_hh[TOT];
__device__ __half g_h1[TOT];
__device__ __half g_waH[SEQ * SEQ];
__device__ __half g_wqhi[CH * CH];
__device__ __half g_wqlo[CH * CH];
__device__ __half g_w1H[CH * CH];
__device__ __half g_w2H[CH * CH];

// ---------------------------------------------------------------------------
// helpers
// ---------------------------------------------------------------------------
__device__ __forceinline__ float gelu_exact(float v)
{
    return 0.5f * v * (1.0f + erff(v * 0.7071067811865476f));
}

__device__ __forceinline__ void h_split(float x, __half& hi, __half& lo)
{
    hi = __float2half_rn(x);
    lo = __float2half_rn(x - __half2float(hi));
}

__device__ __forceinline__ unsigned pack_h2(float a, float b)
{
    __half2 h = __floats2half2_rn(a, b);
    return *(unsigned*)&h;
}

__device__ __forceinline__ void mma_f16(float* c, const unsigned* a, const unsigned* b)
{
    asm volatile(
        "mma.sync.aligned.m16n8k16.row.col.f32.f16.f16.f32 "
        "{%0,%1,%2,%3}, {%4,%5,%6,%7}, {%8,%9}, {%0,%1,%2,%3};"
        : "+f"(c[0]), "+f"(c[1]), "+f"(c[2]), "+f"(c[3])
        : "r"(a[0]), "r"(a[1]), "r"(a[2]), "r"(a[3]), "r"(b[0]), "r"(b[1]));
}

__device__ __forceinline__ unsigned smaddr(const void* p)
{
    return (unsigned)__cvta_generic_to_shared(p);
}

__device__ __forceinline__ void ldsm_x4(unsigned* r, const void* p)
{
    asm volatile("ldmatrix.sync.aligned.m8n8.x4.shared.b16 {%0,%1,%2,%3}, [%4];"
        : "=r"(r[0]), "=r"(r[1]), "=r"(r[2]), "=r"(r[3]) : "r"(smaddr(p)));
}

__device__ __forceinline__ void cp_async16(void* smem, const void* gmem)
{
    asm volatile("cp.async.cg.shared.global [%0], [%1], 16;"
        :: "r"(smaddr(smem)), "l"(gmem));
}
#define CP_COMMIT() asm volatile("cp.async.commit_group;")
#define CP_WAIT0()  asm volatile("cp.async.wait_group 0;")
#define CP_WAIT1()  asm volatile("cp.async.wait_group 1;")

// ---------------------------------------------------------------------------
// RMSNorm reduce helper
// ---------------------------------------------------------------------------
__device__ __forceinline__ float rms_inv(float v0, float v1, float v2, int t)
{
    float ss = v0 * v0 + v1 * v1 + v2 * v2;
    __shared__ float red[8];
    #pragma unroll
    for (int o = 16; o > 0; o >>= 1) ss += __shfl_xor_sync(0xffffffffu, ss, o);
    if ((t & 31) == 0) red[t >> 5] = ss;
    __syncthreads();
    if (t < 8) {
        float s = red[t];
        #pragma unroll
        for (int o = 4; o > 0; o >>= 1) s += __shfl_xor_sync(0xffu, s, o);
        if (t == 0) red[0] = s;
    }
    __syncthreads();
    return rsqrtf(red[0] * (1.0f / 768.0f) + 1.1920928955078125e-07f);
}

// ---------------------------------------------------------------------------
// Fused prep: blocks [0, ROWS) -> rmsnorm1+split of x; blocks >= ROWS ->
// weight conversion (WA/W1/W2 -> half ; Wq -> hi/lo split).
// ---------------------------------------------------------------------------
#define N_WA (SEQ * SEQ / 4)
#define N_W  (CH * CH / 4)
#define ROWS_G (BATCH * SEQ)

__global__ __launch_bounds__(256)
void prep_kernel(const float* __restrict__ x, const float* __restrict__ g1,
                 __half* __restrict__ xhi, __half* __restrict__ xlo,
                 const float* __restrict__ WA, const float* __restrict__ W1,
                 const float* __restrict__ W2, const float* __restrict__ Wq,
                 __half* __restrict__ waH, __half* __restrict__ w1H,
                 __half* __restrict__ w2H,
                 __half* __restrict__ wqhi, __half* __restrict__ wqlo)
{
    const int t = threadIdx.x;
    if (blockIdx.x < ROWS_G) {
        const int row = blockIdx.x;
        const float* xr = x + (long)row * CH;
        float v0 = xr[t], v1 = xr[t + 256], v2 = xr[t + 512];
        const float inv = rms_inv(v0, v1, v2, t);
        __half h, l;
        h_split(v0 * inv * g1[t], h, l);
        xhi[(long)row * CH + t] = h; xlo[(long)row * CH + t] = l;
        h_split(v1 * inv * g1[t + 256], h, l);
        xhi[(long)row * CH + t + 256] = h; xlo[(long)row * CH + t + 256] = l;
        h_split(v2 * inv * g1[t + 512], h, l);
        xhi[(long)row * CH + t + 512] = h; xlo[(long)row * CH + t + 512] = l;
        return;
    }
    long i = (long)(blockIdx.x - ROWS_G) * blockDim.x + t;
    const float* src;
    __half* dst;
    if (i < N_WA) { src = WA; dst = waH; }
    else if ((i -= N_WA) < N_W) { src = W1; dst = w1H; }
    else if ((i -= N_W) < N_W)  { src = W2; dst = w2H; }
    else if ((i -= N_W) < N_W) {
        const long e = i * 4;
        float4 v = *(const float4*)(Wq + e);
        __half h0, l0, h1, l1, h2, l2, h3, l3;
        h_split(v.x, h0, l0); h_split(v.y, h1, l1);
        h_split(v.z, h2, l2); h_split(v.w, h3, l3);
        *(__half2*)(wqhi + e)     = __halves2half2(h0, h1);
        *(__half2*)(wqhi + e + 2) = __halves2half2(h2, h3);
        *(__half2*)(wqlo + e)     = __halves2half2(l0, l1);
        *(__half2*)(wqlo + e + 2) = __halves2half2(l2, l3);
        return;
    } else return;
    const long e = i * 4;
    float4 v = *(const float4*)(src + e);
    *(__half2*)(dst + e)     = __floats2half2_rn(v.x, v.y);
    *(__half2*)(dst + e + 2) = __floats2half2_rn(v.z, v.w);
}

__global__ __launch_bounds__(256)
void rmsnorm_h_kernel(const float* __restrict__ x, const float* __restrict__ g,
                      __half* __restrict__ y)
{
    const int row = blockIdx.x;
    const int t = threadIdx.x;
    const float* xr = x + (long)row * CH;
    float v0 = xr[t], v1 = xr[t + 256], v2 = xr[t + 512];
    const float inv = rms_inv(v0, v1, v2, t);
    __half* yr = y + (long)row * CH;
    yr[t]       = __float2half_rn(v0 * inv * g[t]);
    yr[t + 256] = __float2half_rn(v1 * inv * g[t + 256]);
    yr[t + 512] = __float2half_rn(v2 * inv * g[t + 512]);
}

// ---------------------------------------------------------------------------
// Transpose-gather: xhi (H,N,HD flat view, half) -> vpT[b][c][token]
// ---------------------------------------------------------------------------
__global__ __launch_bounds__(256)
void tr_gather_kernel(const __half* __restrict__ xhi, __half* __restrict__ vpT)
{
    __shared__ __half smt[32][34];
    const int b = blockIdx.z, h = blockIdx.y, m0 = blockIdx.x * 32;
    const int tx = threadIdx.x & 31, ty = threadIdx.x >> 5;
    const __half* src = xhi + (long)b * L_PER_B + (long)h * (SEQ * HD);
    #pragma unroll
    for (int i = 0; i < 4; i++)
        smt[ty + 8 * i][tx] = src[(long)(m0 + ty + 8 * i) * HD + tx];
    __syncthreads();
    __half* dst = vpT + (long)b * L_PER_B;
    #pragma unroll
    for (int i = 0; i < 4; i++) {
        const int d = ty + 8 * i;
        dst[(long)(h * 32 + d) * SEQ + m0 + tx] = smt[tx][d];
    }
}

// ---------------------------------------------------------------------------
// fp16 NT GEMM: C[m][n] = sum_k A[m][k] * B[n][k], 128x128x32 tile, ldmatrix,
// 3-stage cp.async pipeline, one sync per tile, 3 blocks/SM.
// EPI: 0 -> fp32 C ; 1 -> exact GELU, half Ch ; 2 -> +R, fp32 C ; 3 -> half Ch
// ---------------------------------------------------------------------------
#define GH_BUF 5120
#define GH_SMEM_BYTES (6 * GH_BUF * 2)

template<int EPI>
__global__ __launch_bounds__(256, 3)
void gemm_h(const __half* __restrict__ A, const __half* __restrict__ B,
            float* __restrict__ C, __half* __restrict__ Ch,
            const float* __restrict__ R,
            int M, int N, int K, long sA, long sB, long sC)
{
    extern __shared__ __half smh[];
    __half* Asm = smh;
    __half* Bsm = smh + 3 * GH_BUF;

    A += (long)blockIdx.z * sA;
    B += (long)blockIdx.z * sB;
    if (EPI == 1 || EPI == 3) Ch += (long)blockIdx.z * sC;
    else                      C  += (long)blockIdx.z * sC;
    if (EPI == 2) R += (long)blockIdx.z * sC;

    const int t = threadIdx.x;
    const int w = t >> 5, lane = t & 31;
    const int g = lane >> 2, tg = lane & 3;
    const int wm = w >> 2, wn = w & 3;
    const int m0 = blockIdx.y * 128, n0 = blockIdx.x * 128;
    const int nk = K >> 5;

    const int jj = lane >> 3, r8 = lane & 7;
    const int aRow = (jj & 1) * 8 + r8, aCol = (jj >> 1) * 8;
    const int bRow = (jj >> 1) * 8 + r8, bCol = (jj & 1) * 8;

    auto stage = [&](int s, int k0) {
        __half* as = Asm + s * GH_BUF;
        __half* bs = Bsm + s * GH_BUF;
        #pragma unroll
        for (int i = 0; i < 2; i++) {
            const int f = t + i * 256;
            const int row = f >> 2, seg = f & 3;
            cp_async16(&as[row * 40 + seg * 8], A + (long)(m0 + row) * K + k0 + seg * 8);
            cp_async16(&bs[row * 40 + seg * 8], B + (long)(n0 + row) * K + k0 + seg * 8);
        }
    };

    float acc[4][4][4] = {};

    stage(0, 0);
    CP_COMMIT();
    if (nk > 1) { stage(1, 32); CP_COMMIT(); }

    int sb = 0;                       // buffer index of tile kt
    for (int kt = 0; kt < nk; kt++) {
        if (kt + 1 < nk) { CP_WAIT1(); } else { CP_WAIT0(); }
        __syncthreads();
        if (kt + 2 < nk) {
            stage((sb + 2) % 3, (kt + 2) * 32);
            CP_COMMIT();
        }

        const __half* as = Asm + sb * GH_BUF;
        const __half* bs = Bsm + sb * GH_BUF;

        #pragma unroll
        for (int kc = 0; kc < 2; kc++) {
            const int kb = kc * 16;
            unsigned a[4][4], b2[2][4];
            #pragma unroll
            for (int mt = 0; mt < 4; mt++)
                ldsm_x4(a[mt], &as[(wm * 64 + mt * 16 + aRow) * 40 + kb + aCol]);
            #pragma unroll
            for (int np = 0; np < 2; np++)
                ldsm_x4(b2[np], &bs[(wn * 32 + np * 16 + bRow) * 40 + kb + bCol]);
            #pragma unroll
            for (int mt = 0; mt < 4; mt++)
                #pragma unroll
                for (int nt = 0; nt < 4; nt++)
                    mma_f16(acc[mt][nt], a[mt], &b2[nt >> 1][(nt & 1) * 2]);
        }
        sb = (sb + 1) % 3;
    }

    #pragma unroll
    for (int mt = 0; mt < 4; mt++) {
        #pragma unroll
        for (int nt = 0; nt < 4; nt++) {
            const int row0 = m0 + wm * 64 + mt * 16 + g;
            const int col  = n0 + wn * 32 + nt * 8 + 2 * tg;
            float v0 = acc[mt][nt][0], v1 = acc[mt][nt][1];
            float v2 = acc[mt][nt][2], v3 = acc[mt][nt][3];
            if (EPI == 1 || EPI == 3) {
                if (EPI == 1) {
                    v0 = gelu_exact(v0); v1 = gelu_exact(v1);
                    v2 = gelu_exact(v2); v3 = gelu_exact(v3);
                }
                *(__half2*)(Ch + (long)row0 * N + col) = __floats2half2_rn(v0, v1);
                *(__half2*)(Ch + (long)(row0 + 8) * N + col) = __floats2half2_rn(v2, v3);
            } else {
                if (EPI == 2) {
                    float2 r0 = *(const float2*)(R + (long)row0 * N + col);
                    float2 r1 = *(const float2*)(R + (long)(row0 + 8) * N + col);
                    v0 += r0.x; v1 += r0.y; v2 += r1.x; v3 += r1.y;
                }
                float2 o0 = {v0, v1}, o1 = {v2, v3};
                *(float2*)(C + (long)row0 * N + col) = o0;
                *(float2*)(C + (long)(row0 + 8) * N + col) = o1;
            }
        }
    }
}

// ---------------------------------------------------------------------------
// Wq projection: compensated fp16 NT GEMM, pre-split operands, ldmatrix,
// 2-stage pipeline (smem-capped). Epilogue folds coef (head from flat offset).
// ---------------------------------------------------------------------------
#define WQ_SMEM_BYTES (8 * GH_BUF * 2)

__global__ __launch_bounds__(256)
void gemm_wq(const __half* __restrict__ Ahi, const __half* __restrict__ Alo,
             const __half* __restrict__ Bhi, const __half* __restrict__ Blo,
             __half* __restrict__ Chi, __half* __restrict__ Clo,
             const float* __restrict__ scale_param, int M, int N, int K)
{
    extern __shared__ __half smw[];
    __half* AH = smw;
    __half* AL = smw + 2 * GH_BUF;
    __half* BH = smw + 4 * GH_BUF;
    __half* BL = smw + 6 * GH_BUF;
    __shared__ float scoef[HEADS];

    const int t = threadIdx.x;
    if (t < HEADS)
        scoef[t] = logf(768.0f) * scale_param[t] * 5.656854249492381f;

    const int w = t >> 5, lane = t & 31;
    const int g = lane >> 2, tg = lane & 3;
    const int wm = w >> 2, wn = w & 3;
    const int m0 = blockIdx.y * 128, n0 = blockIdx.x * 128;
    const int nk = K >> 5;

    const int jj = lane >> 3, r8 = lane & 7;
    const int aRow = (jj & 1) * 8 + r8, aCol = (jj >> 1) * 8;
    const int bRow = (jj >> 1) * 8 + r8, bCol = (jj & 1) * 8;

    auto stage = [&](int s, int k0) {
        __half* ah = AH + s * GH_BUF;
        __half* al = AL + s * GH_BUF;
        __half* bh = BH + s * GH_BUF;
        __half* bl = BL + s * GH_BUF;
        #pragma unroll
        for (int i = 0; i < 2; i++) {
            const int f = t + i * 256;
            const int row = f >> 2, seg = f & 3;
            const long asrc = (long)(m0 + row) * K + k0 + seg * 8;
            const long bsrc = (long)(n0 + row) * K + k0 + seg * 8;
            cp_async16(&ah[row * 40 + seg * 8], Ahi + asrc);
            cp_async16(&al[row * 40 + seg * 8], Alo + asrc);
            cp_async16(&bh[row * 40 + seg * 8], Bhi + bsrc);
            cp_async16(&bl[row * 40 + seg * 8], Blo + bsrc);
        }
    };

    float acc[4][4][4] = {};

    stage(0, 0);
    CP_COMMIT();

    for (int kt = 0; kt < nk; kt++) {
        CP_WAIT0();
        __syncthreads();
        if (kt + 1 < nk) {
            stage((kt + 1) & 1, (kt + 1) * 32);
            CP_COMMIT();
        }

        const __half* ah = AH + (kt & 1) * GH_BUF;
        const __half* al = AL + (kt & 1) * GH_BUF;
        const __half* bh = BH + (kt & 1) * GH_BUF;
        const __half* bl = BL + (kt & 1) * GH_BUF;

        #pragma unroll
        for (int kc = 0; kc < 2; kc++) {
            const int kb = kc * 16;
            unsigned aH[4][4], aL[4][4], bH2[2][4], bL2[2][4];
            #pragma unroll
            for (int mt = 0; mt < 4; mt++) {
                const int ao = (wm * 64 + mt * 16 + aRow) * 40 + kb + aCol;
                ldsm_x4(aH[mt], &ah[ao]);
                ldsm_x4(aL[mt], &al[ao]);
            }
            #pragma unroll
            for (int np = 0; np < 2; np++) {
                const int bo = (wn * 32 + np * 16 + bRow) * 40 + kb + bCol;
                ldsm_x4(bH2[np], &bh[bo]);
                ldsm_x4(bL2[np], &bl[bo]);
            }
            #pragma unroll
            for (int mt = 0; mt < 4; mt++)
                #pragma unroll
                for (int nt = 0; nt < 4; nt++) {
                    const unsigned* pbh = &bH2[nt >> 1][(nt & 1) * 2];
                    const unsigned* pbl = &bL2[nt >> 1][(nt & 1) * 2];
                    mma_f16(acc[mt][nt], aH[mt], pbh);
                    mma_f16(acc[mt][nt], aH[mt], pbl);
                    mma_f16(acc[mt][nt], aL[mt], pbh);
                }
        }
        __syncthreads();
    }

    #pragma unroll
    for (int mt = 0; mt < 4; mt++) {
        #pragma unroll
        for (int nt = 0; nt < 4; nt++) {
            const int row0 = m0 + wm * 64 + mt * 16 + g;
            const int col  = n0 + wn * 32 + nt * 8 + 2 * tg;
            const int n0b = row0 & (SEQ - 1);
            const int f00 = n0b * CH + col;
            const int f10 = (n0b + 8) * CH + col;
            const float c00 = scoef[f00 >> 16];
            const float c01 = scoef[(f00 + 1) >> 16];
            const float c10 = scoef[f10 >> 16];
            const float c11 = scoef[(f10 + 1) >> 16];
            float v0 = acc[mt][nt][0] * c00, v1 = acc[mt][nt][1] * c01;
            float v2 = acc[mt][nt][2] * c10, v3 = acc[mt][nt][3] * c11;
            __half h0, l0, h1, l1, h2, l2, h3, l3;
            h_split(v0, h0, l0); h_split(v1, h1, l1);
            h_split(v2, h2, l2); h_split(v3, h3, l3);
            *(__half2*)(Chi + (long)row0 * N + col) = __halves2half2(h0, h1);
            *(__half2*)(Clo + (long)row0 * N + col) = __halves2half2(l0, l1);
            *(__half2*)(Chi + (long)(row0 + 8) * N + col) = __halves2half2(h2, h3);
            *(__half2*)(Clo + (long)(row0 + 8) * N + col) = __halves2half2(l2, l3);
        }
    }
}

// ---------------------------------------------------------------------------
// fp16 flash attention with ldmatrix fragment loads, 2-stage pipeline.
// QK: hi/lo 3-term fp16. PV: single fp16.
// ---------------------------------------------------------------------------
#define FK_HI(s) ((s) * 2560)
#define FK_LO(s) (5120 + (s) * 2560)
#define FV(s)    (10240 + (s) * 2304)
#define FLASH_SMEM_BYTES (14848 * 2)

__global__ __launch_bounds__(256, 2)
void flash_h(const __half* __restrict__ Qhi, const __half* __restrict__ Qlo,
             const __half* __restrict__ Khi, const __half* __restrict__ Klo,
             const __half* __restrict__ VT,
             const float* __restrict__ X, float* __restrict__ O)
{
    extern __shared__ __half smf[];

    const int b = blockIdx.z, h = blockIdx.y;
    const int t = threadIdx.x, w = t >> 5, lane = t & 31;
    const int g = lane >> 2, tg = lane & 3;
    const long baseqk = (long)b * L_PER_B + (long)h * (SEQ * HD);
    const long basevT = (long)b * L_PER_B + (long)(h * HD) * SEQ;

    const int row0 = blockIdx.x * 128 + w * 16 + g;

    const int jj = lane >> 3, r8 = lane & 7;
    const int bRow = (jj >> 1) * 8 + r8, bCol = (jj & 1) * 8;

    auto stage = [&](int s, int kt) {
        __half* kh = smf + FK_HI(s);
        __half* kl = smf + FK_LO(s);
        __half* vh = smf + FV(s);
        {
            const int row = t >> 2, seg = t & 3;
            const long src = baseqk + (long)(kt * 64 + row) * HD + seg * 8;
            cp_async16(&kh[row * 40 + seg * 8], Khi + src);
            cp_async16(&kl[row * 40 + seg * 8], Klo + src);
        }
        {
            const int d = t >> 3, seg = t & 7;
            const long src = basevT + (long)d * SEQ + kt * 64 + seg * 8;
            cp_async16(&vh[d * 72 + seg * 8], VT + src);
        }
    };

    unsigned qh[2][4], ql[2][4];
    #pragma unroll
    for (int kc = 0; kc < 2; kc++) {
        #pragma unroll
        for (int rr = 0; rr < 2; rr++) {
            const long base = baseqk + (long)(row0 + rr * 8) * HD + kc * 16 + 2 * tg;
            qh[kc][rr]     = *(const unsigned*)&Qhi[base];
            qh[kc][rr + 2] = *(const unsigned*)&Qhi[base + 8];
            ql[kc][rr]     = *(const unsigned*)&Qlo[base];
            ql[kc][rr + 2] = *(const unsigned*)&Qlo[base + 8];
        }
    }

    float acco[4][4] = {};
    float Mx[2] = {-1e30f, -1e30f};
    float Srun[2] = {0.0f, 0.0f};
    const unsigned full = 0xffffffffu;

    stage(0, 0);
    CP_COMMIT();

    for (int kt = 0; kt < SEQ / 64; kt++) {
        CP_WAIT0();
        __syncthreads();
        if (kt + 1 < SEQ / 64) {
            stage((kt + 1) & 1, kt + 1);
            CP_COMMIT();
        }

        const int s = kt & 1;
        const __half* ksh_hi = smf + FK_HI(s);
        const __half* ksh_lo = smf + FK_LO(s);
        const __half* vsh = smf + FV(s);

        // ---- S = Q K^T (ldmatrix K-frags) ----
        float accs[8][4] = {};
        #pragma unroll
        for (int kc = 0; kc < 2; kc++) {
            const int kb = kc * 16;
            #pragma unroll
            for (int np = 0; np < 4; np++) {
                unsigned bh4[4], bl4[4];
                const int ko = (np * 16 + bRow) * 40 + kb + bCol;
                ldsm_x4(bh4, &ksh_hi[ko]);
                ldsm_x4(bl4, &ksh_lo[ko]);
                #pragma unroll
                for (int q = 0; q < 2; q++) {
                    const int nt = np * 2 + q;
                    mma_f16(accs[nt], qh[kc], &bh4[q * 2]);
                    mma_f16(accs[nt], qh[kc], &bl4[q * 2]);
                    mma_f16(accs[nt], ql[kc], &bh4[q * 2]);
                }
            }
        }

        // ---- online softmax ----
        #pragma unroll
        for (int rr = 0; rr < 2; rr++) {
            const int i0 = rr * 2, i1 = rr * 2 + 1;
            float m = accs[0][i0];
            #pragma unroll
            for (int nt = 0; nt < 8; nt++) {
                m = fmaxf(m, accs[nt][i0]);
                m = fmaxf(m, accs[nt][i1]);
            }
            m = fmaxf(m, __shfl_xor_sync(full, m, 1));
            m = fmaxf(m, __shfl_xor_sync(full, m, 2));
            const float Mn = fmaxf(Mx[rr], m);
            const float corr = __expf(Mx[rr] - Mn);
            Srun[rr] *= corr;
            #pragma unroll
            for (int nt = 0; nt < 4; nt++) {
                acco[nt][i0] *= corr;
                acco[nt][i1] *= corr;
            }
            Mx[rr] = Mn;
            float lsum = 0.0f;
            #pragma unroll
            for (int nt = 0; nt < 8; nt++) {
                const float p0 = __expf(accs[nt][i0] - Mn);
                const float p1 = __expf(accs[nt][i1] - Mn);
                lsum += p0 + p1;
                accs[nt][i0] = p0;
                accs[nt][i1] = p1;
            }
            lsum += __shfl_xor_sync(full, lsum, 1);
            lsum += __shfl_xor_sync(full, lsum, 2);
            Srun[rr] += lsum;
        }

        // ---- pack P to fp16 A-fragments ----
        unsigned ph[8][2];
        #pragma unroll
        for (int nt = 0; nt < 8; nt++) {
            ph[nt][0] = pack_h2(accs[nt][0], accs[nt][1]);
            ph[nt][1] = pack_h2(accs[nt][2], accs[nt][3]);
        }

        // ---- O += P V (ldmatrix V-frags) ----
        #pragma unroll
        for (int kcK = 0; kcK < 4; kcK++) {
            unsigned pa[4] = {ph[2 * kcK][0], ph[2 * kcK][1],
                              ph[2 * kcK + 1][0], ph[2 * kcK + 1][1]};
            #pragma unroll
            for (int vp = 0; vp < 2; vp++) {
                unsigned v4[4];
                ldsm_x4(v4, &vsh[(vp * 16 + bRow) * 72 + kcK * 16 + bCol]);
                mma_f16(acco[vp * 2],     pa, &v4[0]);
                mma_f16(acco[vp * 2 + 1], pa, &v4[2]);
            }
        }
        __syncthreads();
    }

    // ---- epilogue: /S, +x, store ----
    const float inv0 = 1.0f / Srun[0];
    const float inv1 = 1.0f / Srun[1];
    #pragma unroll
    for (int nt = 0; nt < 4; nt++) {
        const int col = nt * 8 + 2 * tg;
        const long a0 = baseqk + (long)row0 * HD + col;
        const long a1 = baseqk + (long)(row0 + 8) * HD + col;
        float2 x0 = *(const float2*)(X + a0);
        float2 x1 = *(const float2*)(X + a1);
        float2 o0 = {acco[nt][0] * inv0 + x0.x, acco[nt][1] * inv0 + x0.y};
        float2 o1 = {acco[nt][2] * inv1 + x1.x, acco[nt][3] * inv1 + x1.y};
        *(float2*)(O + a0) = o0;
        *(float2*)(O + a1) = o1;
    }
}

// ---------------------------------------------------------------------------
// Launch
// ---------------------------------------------------------------------------
extern "C" void kernel_launch(void* const* d_in, const int* in_sizes, int n_in,
                              void* d_out, int out_size)
{
    const float* x     = (const float*)d_in[0];
    const float* scale = (const float*)d_in[1];
    const float* Wq    = (const float*)d_in[2];
    const float* WA    = (const float*)d_in[3];
    const float* W1    = (const float*)d_in[4];
    const float* W2    = (const float*)d_in[5];
    const float* g1    = (const float*)d_in[6];
    const float* g2    = (const float*)d_in[7];
    float* out = (float*)d_out;

    float *res;
    __half *xhi, *xlo, *qhi, *qlo, *vpT, *vT, *hh, *h1;
    __half *waH, *wqhi, *wqlo, *w1H, *w2H;
    cudaGetSymbolAddress((void**)&res,  g_res);
    cudaGetSymbolAddress((void**)&xhi,  g_xhi);
    cudaGetSymbolAddress((void**)&xlo,  g_xlo);
    cudaGetSymbolAddress((void**)&qhi,  g_qhi);
    cudaGetSymbolAddress((void**)&qlo,  g_qlo);
    cudaGetSymbolAddress((void**)&vpT,  g_vpT);
    cudaGetSymbolAddress((void**)&vT,   g_vT);
    cudaGetSymbolAddress((void**)&hh,   g_hh);
    cudaGetSymbolAddress((void**)&h1,   g_h1);
    cudaGetSymbolAddress((void**)&waH,  g_waH);
    cudaGetSymbolAddress((void**)&wqhi, g_wqhi);
    cudaGetSymbolAddress((void**)&wqlo, g_wqlo);
    cudaGetSymbolAddress((void**)&w1H,  g_w1H);
    cudaGetSymbolAddress((void**)&w2H,  g_w2H);

    const int ROWS = BATCH * SEQ;  // 4096

    cudaFuncSetAttribute(gemm_wq, cudaFuncAttributeMaxDynamicSharedMemorySize,
                         WQ_SMEM_BYTES);
    cudaFuncSetAttribute(flash_h, cudaFuncAttributeMaxDynamicSharedMemorySize,
                         FLASH_SMEM_BYTES);
    cudaFuncSetAttribute(gemm_h<1>, cudaFuncAttributeMaxDynamicSharedMemorySize,
                         GH_SMEM_BYTES);
    cudaFuncSetAttribute(gemm_h<2>, cudaFuncAttributeMaxDynamicSharedMemorySize,
                         GH_SMEM_BYTES);
    cudaFuncSetAttribute(gemm_h<3>, cudaFuncAttributeMaxDynamicSharedMemorySize,
                         GH_SMEM_BYTES);

    // 0+1. fused: rmsnorm1+split of x AND weight prep, one launch
    const int prepBlocks = (N_WA + 3 * N_W + 255) / 256;
    prep_kernel<<<ROWS + prepBlocks, 256>>>(
        x, g1, xhi, xlo, WA, W1, W2, Wq, waH, w1H, w2H, wqhi, wqlo);

    // 2. q = (xn @ Wq^T) * coef(head(flat)) -> half hi/lo (compensated fp16)
    gemm_wq<<<dim3(CH / 128, ROWS / 128, 1), 256, WQ_SMEM_BYTES>>>(
        xhi, xlo, wqhi, wqlo, qhi, qlo, scale, ROWS, CH, CH);

    // 3. transpose-gather V' -> vpT[b][c][token]
    tr_gather_kernel<<<dim3(SEQ / 32, HEADS, BATCH), 256>>>(xhi, vpT);

    // 4. vT[b][c][m] = NT(vpT, waH) — premix with direct transposed half output
    gemm_h<3><<<dim3(SEQ / 128, CH / 128, BATCH), 256, GH_SMEM_BYTES>>>(
        vpT, waH, nullptr, vT, nullptr, CH, SEQ, SEQ,
        (long)L_PER_B, 0, (long)L_PER_B);

    // 5. attention (+x residual)
    flash_h<<<dim3(SEQ / 128, HEADS, BATCH), 256, FLASH_SMEM_BYTES>>>(
        qhi, qlo, xhi, xlo, vT, x, res);

    // 6. hh = rmsnorm(res, g2) -> half
    rmsnorm_h_kernel<<<ROWS, 256>>>(res, g2, hh);

    // 7. h1 = gelu(hh @ W1^T) -> half
    gemm_h<1><<<dim3(CH / 128, ROWS / 128, 1), 256, GH_SMEM_BYTES>>>(
        hh, w1H, nullptr, h1, nullptr, ROWS, CH, CH, 0, 0, 0);

    // 8. out = h1 @ W2^T + res
    gemm_h<2><<<dim3(CH / 128, ROWS / 128, 1), 256, GH_SMEM_BYTES>>>(
        h1, w2H, out, nullptr, res, ROWS, CH, CH, 0, 0, 0);
}

// round 16
// speedup vs baseline: 1.0813x; 1.0813x over previous
#include <cuda_runtime.h>
#include <cuda_fp16.h>
#include <math.h>

// ---------------------------------------------------------------------------
// Problem constants
// ---------------------------------------------------------------------------
#define BATCH 2
#define SEQ   2048
#define CH    768
#define HEADS 24
#define HD    32
#define L_PER_B (SEQ * CH)
#define TOT (BATCH * SEQ * CH)

// fp32 scratch
__device__ float g_res[TOT];
// half scratch
__device__ __half g_xhi[TOT];
__device__ __half g_xlo[TOT];
__device__ __half g_qhi[TOT];
__device__ __half g_qlo[TOT];
__device__ __half g_vpT[TOT];     // [b][c][token]
__device__ __half g_vT[TOT];      // [b][c][token]
__device__ __half g_hh[TOT];
__device__ __half g_h1[TOT];
__device__ __half g_waH[SEQ * SEQ];
__device__ __half g_wqhi[CH * CH];
__device__ __half g_wqlo[CH * CH];
__device__ __half g_w1H[CH * CH];
__device__ __half g_w2H[CH * CH];

// ---------------------------------------------------------------------------
// helpers
// ---------------------------------------------------------------------------
__device__ __forceinline__ float gelu_exact(float v)
{
    return 0.5f * v * (1.0f + erff(v * 0.7071067811865476f));
}

__device__ __forceinline__ void h_split(float x, __half& hi, __half& lo)
{
    hi = __float2half_rn(x);
    lo = __float2half_rn(x - __half2float(hi));
}

__device__ __forceinline__ unsigned pack_h2(float a, float b)
{
    __half2 h = __floats2half2_rn(a, b);
    return *(unsigned*)&h;
}

__device__ __forceinline__ void mma_f16(float* c, const unsigned* a, const unsigned* b)
{
    asm volatile(
        "mma.sync.aligned.m16n8k16.row.col.f32.f16.f16.f32 "
        "{%0,%1,%2,%3}, {%4,%5,%6,%7}, {%8,%9}, {%0,%1,%2,%3};"
        : "+f"(c[0]), "+f"(c[1]), "+f"(c[2]), "+f"(c[3])
        : "r"(a[0]), "r"(a[1]), "r"(a[2]), "r"(a[3]), "r"(b[0]), "r"(b[1]));
}

__device__ __forceinline__ unsigned smaddr(const void* p)
{
    return (unsigned)__cvta_generic_to_shared(p);
}

__device__ __forceinline__ void ldsm_x4(unsigned* r, const void* p)
{
    asm volatile("ldmatrix.sync.aligned.m8n8.x4.shared.b16 {%0,%1,%2,%3}, [%4];"
        : "=r"(r[0]), "=r"(r[1]), "=r"(r[2]), "=r"(r[3]) : "r"(smaddr(p)));
}

__device__ __forceinline__ void cp_async16(void* smem, const void* gmem)
{
    asm volatile("cp.async.cg.shared.global [%0], [%1], 16;"
        :: "r"(smaddr(smem)), "l"(gmem));
}
#define CP_COMMIT() asm volatile("cp.async.commit_group;")
#define CP_WAIT0()  asm volatile("cp.async.wait_group 0;")
#define CP_WAIT1()  asm volatile("cp.async.wait_group 1;")

// ---------------------------------------------------------------------------
// RMSNorm reduce helper
// ---------------------------------------------------------------------------
__device__ __forceinline__ float rms_inv(float v0, float v1, float v2, int t)
{
    float ss = v0 * v0 + v1 * v1 + v2 * v2;
    __shared__ float red[8];
    #pragma unroll
    for (int o = 16; o > 0; o >>= 1) ss += __shfl_xor_sync(0xffffffffu, ss, o);
    if ((t & 31) == 0) red[t >> 5] = ss;
    __syncthreads();
    if (t < 8) {
        float s = red[t];
        #pragma unroll
        for (int o = 4; o > 0; o >>= 1) s += __shfl_xor_sync(0xffu, s, o);
        if (t == 0) red[0] = s;
    }
    __syncthreads();
    return rsqrtf(red[0] * (1.0f / 768.0f) + 1.1920928955078125e-07f);
}

// ---------------------------------------------------------------------------
// Fused prep: blocks [0, ROWS) -> rmsnorm1+split of x; blocks >= ROWS ->
// weight conversion (WA/W1/W2 -> half ; Wq -> hi/lo split).
// ---------------------------------------------------------------------------
#define N_WA (SEQ * SEQ / 4)
#define N_W  (CH * CH / 4)
#define ROWS_G (BATCH * SEQ)

__global__ __launch_bounds__(256)
void prep_kernel(const float* __restrict__ x, const float* __restrict__ g1,
                 __half* __restrict__ xhi, __half* __restrict__ xlo,
                 const float* __restrict__ WA, const float* __restrict__ W1,
                 const float* __restrict__ W2, const float* __restrict__ Wq,
                 __half* __restrict__ waH, __half* __restrict__ w1H,
                 __half* __restrict__ w2H,
                 __half* __restrict__ wqhi, __half* __restrict__ wqlo)
{
    const int t = threadIdx.x;
    if (blockIdx.x < ROWS_G) {
        const int row = blockIdx.x;
        const float* xr = x + (long)row * CH;
        float v0 = xr[t], v1 = xr[t + 256], v2 = xr[t + 512];
        const float inv = rms_inv(v0, v1, v2, t);
        __half h, l;
        h_split(v0 * inv * g1[t], h, l);
        xhi[(long)row * CH + t] = h; xlo[(long)row * CH + t] = l;
        h_split(v1 * inv * g1[t + 256], h, l);
        xhi[(long)row * CH + t + 256] = h; xlo[(long)row * CH + t + 256] = l;
        h_split(v2 * inv * g1[t + 512], h, l);
        xhi[(long)row * CH + t + 512] = h; xlo[(long)row * CH + t + 512] = l;
        return;
    }
    long i = (long)(blockIdx.x - ROWS_G) * blockDim.x + t;
    const float* src;
    __half* dst;
    if (i < N_WA) { src = WA; dst = waH; }
    else if ((i -= N_WA) < N_W) { src = W1; dst = w1H; }
    else if ((i -= N_W) < N_W)  { src = W2; dst = w2H; }
    else if ((i -= N_W) < N_W) {
        const long e = i * 4;
        float4 v = *(const float4*)(Wq + e);
        __half h0, l0, h1, l1, h2, l2, h3, l3;
        h_split(v.x, h0, l0); h_split(v.y, h1, l1);
        h_split(v.z, h2, l2); h_split(v.w, h3, l3);
        *(__half2*)(wqhi + e)     = __halves2half2(h0, h1);
        *(__half2*)(wqhi + e + 2) = __halves2half2(h2, h3);
        *(__half2*)(wqlo + e)     = __halves2half2(l0, l1);
        *(__half2*)(wqlo + e + 2) = __halves2half2(l2, l3);
        return;
    } else return;
    const long e = i * 4;
    float4 v = *(const float4*)(src + e);
    *(__half2*)(dst + e)     = __floats2half2_rn(v.x, v.y);
    *(__half2*)(dst + e + 2) = __floats2half2_rn(v.z, v.w);
}

__global__ __launch_bounds__(256)
void rmsnorm_h_kernel(const float* __restrict__ x, const float* __restrict__ g,
                      __half* __restrict__ y)
{
    const int row = blockIdx.x;
    const int t = threadIdx.x;
    const float* xr = x + (long)row * CH;
    float v0 = xr[t], v1 = xr[t + 256], v2 = xr[t + 512];
    const float inv = rms_inv(v0, v1, v2, t);
    __half* yr = y + (long)row * CH;
    yr[t]       = __float2half_rn(v0 * inv * g[t]);
    yr[t + 256] = __float2half_rn(v1 * inv * g[t + 256]);
    yr[t + 512] = __float2half_rn(v2 * inv * g[t + 512]);
}

// ---------------------------------------------------------------------------
// Transpose-gather: xhi (H,N,HD flat view, half) -> vpT[b][c][token]
// ---------------------------------------------------------------------------
__global__ __launch_bounds__(256)
void tr_gather_kernel(const __half* __restrict__ xhi, __half* __restrict__ vpT)
{
    __shared__ __half smt[32][34];
    const int b = blockIdx.z, h = blockIdx.y, m0 = blockIdx.x * 32;
    const int tx = threadIdx.x & 31, ty = threadIdx.x >> 5;
    const __half* src = xhi + (long)b * L_PER_B + (long)h * (SEQ * HD);
    #pragma unroll
    for (int i = 0; i < 4; i++)
        smt[ty + 8 * i][tx] = src[(long)(m0 + ty + 8 * i) * HD + tx];
    __syncthreads();
    __half* dst = vpT + (long)b * L_PER_B;
    #pragma unroll
    for (int i = 0; i < 4; i++) {
        const int d = ty + 8 * i;
        dst[(long)(h * 32 + d) * SEQ + m0 + tx] = smt[tx][d];
    }
}

// ---------------------------------------------------------------------------
// fp16 NT GEMM: C[m][n] = sum_k A[m][k] * B[n][k], 128x128x32 tile, ldmatrix,
// 3-stage cp.async pipeline (R14 config, no occupancy clamp).
// EPI: 0 -> fp32 C ; 1 -> exact GELU, half Ch ; 2 -> +R, fp32 C ; 3 -> half Ch
// ---------------------------------------------------------------------------
#define GH_BUF 5120
#define GH_SMEM_BYTES (6 * GH_BUF * 2)

template<int EPI>
__global__ __launch_bounds__(256)
void gemm_h(const __half* __restrict__ A, const __half* __restrict__ B,
            float* __restrict__ C, __half* __restrict__ Ch,
            const float* __restrict__ R,
            int M, int N, int K, long sA, long sB, long sC)
{
    extern __shared__ __half smh[];
    __half* Asm = smh;
    __half* Bsm = smh + 3 * GH_BUF;

    A += (long)blockIdx.z * sA;
    B += (long)blockIdx.z * sB;
    if (EPI == 1 || EPI == 3) Ch += (long)blockIdx.z * sC;
    else                      C  += (long)blockIdx.z * sC;
    if (EPI == 2) R += (long)blockIdx.z * sC;

    const int t = threadIdx.x;
    const int w = t >> 5, lane = t & 31;
    const int g = lane >> 2, tg = lane & 3;
    const int wm = w >> 2, wn = w & 3;
    const int m0 = blockIdx.y * 128, n0 = blockIdx.x * 128;
    const int nk = K >> 5;

    const int jj = lane >> 3, r8 = lane & 7;
    const int aRow = (jj & 1) * 8 + r8, aCol = (jj >> 1) * 8;
    const int bRow = (jj >> 1) * 8 + r8, bCol = (jj & 1) * 8;

    auto stage = [&](int s, int k0) {
        __half* as = Asm + s * GH_BUF;
        __half* bs = Bsm + s * GH_BUF;
        #pragma unroll
        for (int i = 0; i < 2; i++) {
            const int f = t + i * 256;
            const int row = f >> 2, seg = f & 3;
            cp_async16(&as[row * 40 + seg * 8], A + (long)(m0 + row) * K + k0 + seg * 8);
            cp_async16(&bs[row * 40 + seg * 8], B + (long)(n0 + row) * K + k0 + seg * 8);
        }
    };

    float acc[4][4][4] = {};

    stage(0, 0);
    CP_COMMIT();
    if (nk > 1) { stage(1, 32); CP_COMMIT(); }

    int sb = 0;                       // buffer index of tile kt
    for (int kt = 0; kt < nk; kt++) {
        if (kt + 1 < nk) { CP_WAIT1(); } else { CP_WAIT0(); }
        __syncthreads();
        if (kt + 2 < nk) {
            stage((sb + 2) % 3, (kt + 2) * 32);
            CP_COMMIT();
        }

        const __half* as = Asm + sb * GH_BUF;
        const __half* bs = Bsm + sb * GH_BUF;

        #pragma unroll
        for (int kc = 0; kc < 2; kc++) {
            const int kb = kc * 16;
            unsigned a[4][4], b2[2][4];
            #pragma unroll
            for (int mt = 0; mt < 4; mt++)
                ldsm_x4(a[mt], &as[(wm * 64 + mt * 16 + aRow) * 40 + kb + aCol]);
            #pragma unroll
            for (int np = 0; np < 2; np++)
                ldsm_x4(b2[np], &bs[(wn * 32 + np * 16 + bRow) * 40 + kb + bCol]);
            #pragma unroll
            for (int mt = 0; mt < 4; mt++)
                #pragma unroll
                for (int nt = 0; nt < 4; nt++)
                    mma_f16(acc[mt][nt], a[mt], &b2[nt >> 1][(nt & 1) * 2]);
        }
        sb = (sb + 1) % 3;
    }

    #pragma unroll
    for (int mt = 0; mt < 4; mt++) {
        #pragma unroll
        for (int nt = 0; nt < 4; nt++) {
            const int row0 = m0 + wm * 64 + mt * 16 + g;
            const int col  = n0 + wn * 32 + nt * 8 + 2 * tg;
            float v0 = acc[mt][nt][0], v1 = acc[mt][nt][1];
            float v2 = acc[mt][nt][2], v3 = acc[mt][nt][3];
            if (EPI == 1 || EPI == 3) {
                if (EPI == 1) {
                    v0 = gelu_exact(v0); v1 = gelu_exact(v1);
                    v2 = gelu_exact(v2); v3 = gelu_exact(v3);
                }
                *(__half2*)(Ch + (long)row0 * N + col) = __floats2half2_rn(v0, v1);
                *(__half2*)(Ch + (long)(row0 + 8) * N + col) = __floats2half2_rn(v2, v3);
            } else {
                if (EPI == 2) {
                    float2 r0 = *(const float2*)(R + (long)row0 * N + col);
                    float2 r1 = *(const float2*)(R + (long)(row0 + 8) * N + col);
                    v0 += r0.x; v1 += r0.y; v2 += r1.x; v3 += r1.y;
                }
                float2 o0 = {v0, v1}, o1 = {v2, v3};
                *(float2*)(C + (long)row0 * N + col) = o0;
                *(float2*)(C + (long)(row0 + 8) * N + col) = o1;
            }
        }
    }
}

// ---------------------------------------------------------------------------
// Wq projection: compensated fp16 NT GEMM, pre-split operands, ldmatrix,
// 2-stage pipeline with prefetch-before-wait (R12 ordering).
// ---------------------------------------------------------------------------
#define WQ_SMEM_BYTES (8 * GH_BUF * 2)

__global__ __launch_bounds__(256)
void gemm_wq(const __half* __restrict__ Ahi, const __half* __restrict__ Alo,
             const __half* __restrict__ Bhi, const __half* __restrict__ Blo,
             __half* __restrict__ Chi, __half* __restrict__ Clo,
             const float* __restrict__ scale_param, int M, int N, int K)
{
    extern __shared__ __half smw[];
    __half* AH = smw;
    __half* AL = smw + 2 * GH_BUF;
    __half* BH = smw + 4 * GH_BUF;
    __half* BL = smw + 6 * GH_BUF;
    __shared__ float scoef[HEADS];

    const int t = threadIdx.x;
    if (t < HEADS)
        scoef[t] = logf(768.0f) * scale_param[t] * 5.656854249492381f;

    const int w = t >> 5, lane = t & 31;
    const int g = lane >> 2, tg = lane & 3;
    const int wm = w >> 2, wn = w & 3;
    const int m0 = blockIdx.y * 128, n0 = blockIdx.x * 128;
    const int nk = K >> 5;

    const int jj = lane >> 3, r8 = lane & 7;
    const int aRow = (jj & 1) * 8 + r8, aCol = (jj >> 1) * 8;
    const int bRow = (jj >> 1) * 8 + r8, bCol = (jj & 1) * 8;

    auto stage = [&](int s, int k0) {
        __half* ah = AH + s * GH_BUF;
        __half* al = AL + s * GH_BUF;
        __half* bh = BH + s * GH_BUF;
        __half* bl = BL + s * GH_BUF;
        #pragma unroll
        for (int i = 0; i < 2; i++) {
            const int f = t + i * 256;
            const int row = f >> 2, seg = f & 3;
            const long asrc = (long)(m0 + row) * K + k0 + seg * 8;
            const long bsrc = (long)(n0 + row) * K + k0 + seg * 8;
            cp_async16(&ah[row * 40 + seg * 8], Ahi + asrc);
            cp_async16(&al[row * 40 + seg * 8], Alo + asrc);
            cp_async16(&bh[row * 40 + seg * 8], Bhi + bsrc);
            cp_async16(&bl[row * 40 + seg * 8], Blo + bsrc);
        }
    };

    float acc[4][4][4] = {};

    stage(0, 0);
    CP_COMMIT();

    for (int kt = 0; kt < nk; kt++) {
        if (kt + 1 < nk) {
            stage((kt + 1) & 1, (kt + 1) * 32);
            CP_COMMIT();
            CP_WAIT1();
        } else {
            CP_WAIT0();
        }
        __syncthreads();

        const __half* ah = AH + (kt & 1) * GH_BUF;
        const __half* al = AL + (kt & 1) * GH_BUF;
        const __half* bh = BH + (kt & 1) * GH_BUF;
        const __half* bl = BL + (kt & 1) * GH_BUF;

        #pragma unroll
        for (int kc = 0; kc < 2; kc++) {
            const int kb = kc * 16;
            unsigned aH[4][4], aL[4][4], bH2[2][4], bL2[2][4];
            #pragma unroll
            for (int mt = 0; mt < 4; mt++) {
                const int ao = (wm * 64 + mt * 16 + aRow) * 40 + kb + aCol;
                ldsm_x4(aH[mt], &ah[ao]);
                ldsm_x4(aL[mt], &al[ao]);
            }
            #pragma unroll
            for (int np = 0; np < 2; np++) {
                const int bo = (wn * 32 + np * 16 + bRow) * 40 + kb + bCol;
                ldsm_x4(bH2[np], &bh[bo]);
                ldsm_x4(bL2[np], &bl[bo]);
            }
            #pragma unroll
            for (int mt = 0; mt < 4; mt++)
                #pragma unroll
                for (int nt = 0; nt < 4; nt++) {
                    const unsigned* pbh = &bH2[nt >> 1][(nt & 1) * 2];
                    const unsigned* pbl = &bL2[nt >> 1][(nt & 1) * 2];
                    mma_f16(acc[mt][nt], aH[mt], pbh);
                    mma_f16(acc[mt][nt], aH[mt], pbl);
                    mma_f16(acc[mt][nt], aL[mt], pbh);
                }
        }
        __syncthreads();
    }

    #pragma unroll
    for (int mt = 0; mt < 4; mt++) {
        #pragma unroll
        for (int nt = 0; nt < 4; nt++) {
            const int row0 = m0 + wm * 64 + mt * 16 + g;
            const int col  = n0 + wn * 32 + nt * 8 + 2 * tg;
            const int n0b = row0 & (SEQ - 1);
            const int f00 = n0b * CH + col;
            const int f10 = (n0b + 8) * CH + col;
            const float c00 = scoef[f00 >> 16];
            const float c01 = scoef[(f00 + 1) >> 16];
            const float c10 = scoef[f10 >> 16];
            const float c11 = scoef[(f10 + 1) >> 16];
            float v0 = acc[mt][nt][0] * c00, v1 = acc[mt][nt][1] * c01;
            float v2 = acc[mt][nt][2] * c10, v3 = acc[mt][nt][3] * c11;
            __half h0, l0, h1, l1, h2, l2, h3, l3;
            h_split(v0, h0, l0); h_split(v1, h1, l1);
            h_split(v2, h2, l2); h_split(v3, h3, l3);
            *(__half2*)(Chi + (long)row0 * N + col) = __halves2half2(h0, h1);
            *(__half2*)(Clo + (long)row0 * N + col) = __halves2half2(l0, l1);
            *(__half2*)(Chi + (long)(row0 + 8) * N + col) = __halves2half2(h2, h3);
            *(__half2*)(Clo + (long)(row0 + 8) * N + col) = __halves2half2(l2, l3);
        }
    }
}

// ---------------------------------------------------------------------------
// fp16 flash attention, ldmatrix frags, 2-stage prefetch-before-wait (R12).
// QK: hi/lo 3-term fp16. PV: single fp16.
// ---------------------------------------------------------------------------
#define FK_HI(s) ((s) * 2560)
#define FK_LO(s) (5120 + (s) * 2560)
#define FV(s)    (10240 + (s) * 2304)
#define FLASH_SMEM_BYTES (14848 * 2)

__global__ __launch_bounds__(256, 2)
void flash_h(const __half* __restrict__ Qhi, const __half* __restrict__ Qlo,
             const __half* __restrict__ Khi, const __half* __restrict__ Klo,
             const __half* __restrict__ VT,
             const float* __restrict__ X, float* __restrict__ O)
{
    extern __shared__ __half smf[];

    const int b = blockIdx.z, h = blockIdx.y;
    const int t = threadIdx.x, w = t >> 5, lane = t & 31;
    const int g = lane >> 2, tg = lane & 3;
    const long baseqk = (long)b * L_PER_B + (long)h * (SEQ * HD);
    const long basevT = (long)b * L_PER_B + (long)(h * HD) * SEQ;

    const int row0 = blockIdx.x * 128 + w * 16 + g;

    const int jj = lane >> 3, r8 = lane & 7;
    const int bRow = (jj >> 1) * 8 + r8, bCol = (jj & 1) * 8;

    auto stage = [&](int s, int kt) {
        __half* kh = smf + FK_HI(s);
        __half* kl = smf + FK_LO(s);
        __half* vh = smf + FV(s);
        {
            const int row = t >> 2, seg = t & 3;
            const long src = baseqk + (long)(kt * 64 + row) * HD + seg * 8;
            cp_async16(&kh[row * 40 + seg * 8], Khi + src);
            cp_async16(&kl[row * 40 + seg * 8], Klo + src);
        }
        {
            const int d = t >> 3, seg = t & 7;
            const long src = basevT + (long)d * SEQ + kt * 64 + seg * 8;
            cp_async16(&vh[d * 72 + seg * 8], VT + src);
        }
    };

    unsigned qh[2][4], ql[2][4];
    #pragma unroll
    for (int kc = 0; kc < 2; kc++) {
        #pragma unroll
        for (int rr = 0; rr < 2; rr++) {
            const long base = baseqk + (long)(row0 + rr * 8) * HD + kc * 16 + 2 * tg;
            qh[kc][rr]     = *(const unsigned*)&Qhi[base];
            qh[kc][rr + 2] = *(const unsigned*)&Qhi[base + 8];
            ql[kc][rr]     = *(const unsigned*)&Qlo[base];
            ql[kc][rr + 2] = *(const unsigned*)&Qlo[base + 8];
        }
    }

    float acco[4][4] = {};
    float Mx[2] = {-1e30f, -1e30f};
    float Srun[2] = {0.0f, 0.0f};
    const unsigned full = 0xffffffffu;

    stage(0, 0);
    CP_COMMIT();

    for (int kt = 0; kt < SEQ / 64; kt++) {
        if (kt + 1 < SEQ / 64) {
            stage((kt + 1) & 1, kt + 1);
            CP_COMMIT();
            CP_WAIT1();
        } else {
            CP_WAIT0();
        }
        __syncthreads();

        const int s = kt & 1;
        const __half* ksh_hi = smf + FK_HI(s);
        const __half* ksh_lo = smf + FK_LO(s);
        const __half* vsh = smf + FV(s);

        // ---- S = Q K^T (ldmatrix K-frags) ----
        float accs[8][4] = {};
        #pragma unroll
        for (int kc = 0; kc < 2; kc++) {
            const int kb = kc * 16;
            #pragma unroll
            for (int np = 0; np < 4; np++) {
                unsigned bh4[4], bl4[4];
                const int ko = (np * 16 + bRow) * 40 + kb + bCol;
                ldsm_x4(bh4, &ksh_hi[ko]);
                ldsm_x4(bl4, &ksh_lo[ko]);
                #pragma unroll
                for (int q = 0; q < 2; q++) {
                    const int nt = np * 2 + q;
                    mma_f16(accs[nt], qh[kc], &bh4[q * 2]);
                    mma_f16(accs[nt], qh[kc], &bl4[q * 2]);
                    mma_f16(accs[nt], ql[kc], &bh4[q * 2]);
                }
            }
        }

        // ---- online softmax ----
        #pragma unroll
        for (int rr = 0; rr < 2; rr++) {
            const int i0 = rr * 2, i1 = rr * 2 + 1;
            float m = accs[0][i0];
            #pragma unroll
            for (int nt = 0; nt < 8; nt++) {
                m = fmaxf(m, accs[nt][i0]);
                m = fmaxf(m, accs[nt][i1]);
            }
            m = fmaxf(m, __shfl_xor_sync(full, m, 1));
            m = fmaxf(m, __shfl_xor_sync(full, m, 2));
            const float Mn = fmaxf(Mx[rr], m);
            const float corr = __expf(Mx[rr] - Mn);
            Srun[rr] *= corr;
            #pragma unroll
            for (int nt = 0; nt < 4; nt++) {
                acco[nt][i0] *= corr;
                acco[nt][i1] *= corr;
            }
            Mx[rr] = Mn;
            float lsum = 0.0f;
            #pragma unroll
            for (int nt = 0; nt < 8; nt++) {
                const float p0 = __expf(accs[nt][i0] - Mn);
                const float p1 = __expf(accs[nt][i1] - Mn);
                lsum += p0 + p1;
                accs[nt][i0] = p0;
                accs[nt][i1] = p1;
            }
            lsum += __shfl_xor_sync(full, lsum, 1);
            lsum += __shfl_xor_sync(full, lsum, 2);
            Srun[rr] += lsum;
        }

        // ---- pack P to fp16 A-fragments ----
        unsigned ph[8][2];
        #pragma unroll
        for (int nt = 0; nt < 8; nt++) {
            ph[nt][0] = pack_h2(accs[nt][0], accs[nt][1]);
            ph[nt][1] = pack_h2(accs[nt][2], accs[nt][3]);
        }

        // ---- O += P V (ldmatrix V-frags) ----
        #pragma unroll
        for (int kcK = 0; kcK < 4; kcK++) {
            unsigned pa[4] = {ph[2 * kcK][0], ph[2 * kcK][1],
                              ph[2 * kcK + 1][0], ph[2 * kcK + 1][1]};
            #pragma unroll
            for (int vp = 0; vp < 2; vp++) {
                unsigned v4[4];
                ldsm_x4(v4, &vsh[(vp * 16 + bRow) * 72 + kcK * 16 + bCol]);
                mma_f16(acco[vp * 2],     pa, &v4[0]);
                mma_f16(acco[vp * 2 + 1], pa, &v4[2]);
            }
        }
        __syncthreads();
    }

    // ---- epilogue: /S, +x, store ----
    const float inv0 = 1.0f / Srun[0];
    const float inv1 = 1.0f / Srun[1];
    #pragma unroll
    for (int nt = 0; nt < 4; nt++) {
        const int col = nt * 8 + 2 * tg;
        const long a0 = baseqk + (long)row0 * HD + col;
        const long a1 = baseqk + (long)(row0 + 8) * HD + col;
        float2 x0 = *(const float2*)(X + a0);
        float2 x1 = *(const float2*)(X + a1);
        float2 o0 = {acco[nt][0] * inv0 + x0.x, acco[nt][1] * inv0 + x0.y};
        float2 o1 = {acco[nt][2] * inv1 + x1.x, acco[nt][3] * inv1 + x1.y};
        *(float2*)(O + a0) = o0;
        *(float2*)(O + a1) = o1;
    }
}

// ---------------------------------------------------------------------------
// Launch
// ---------------------------------------------------------------------------
extern "C" void kernel_launch(void* const* d_in, const int* in_sizes, int n_in,
                              void* d_out, int out_size)
{
    const float* x     = (const float*)d_in[0];
    const float* scale = (const float*)d_in[1];
    const float* Wq    = (const float*)d_in[2];
    const float* WA    = (const float*)d_in[3];
    const float* W1    = (const float*)d_in[4];
    const float* W2    = (const float*)d_in[5];
    const float* g1    = (const float*)d_in[6];
    const float* g2    = (const float*)d_in[7];
    float* out = (float*)d_out;

    float *res;
    __half *xhi, *xlo, *qhi, *qlo, *vpT, *vT, *hh, *h1;
    __half *waH, *wqhi, *wqlo, *w1H, *w2H;
    cudaGetSymbolAddress((void**)&res,  g_res);
    cudaGetSymbolAddress((void**)&xhi,  g_xhi);
    cudaGetSymbolAddress((void**)&xlo,  g_xlo);
    cudaGetSymbolAddress((void**)&qhi,  g_qhi);
    cudaGetSymbolAddress((void**)&qlo,  g_qlo);
    cudaGetSymbolAddress((void**)&vpT,  g_vpT);
    cudaGetSymbolAddress((void**)&vT,   g_vT);
    cudaGetSymbolAddress((void**)&hh,   g_hh);
    cudaGetSymbolAddress((void**)&h1,   g_h1);
    cudaGetSymbolAddress((void**)&waH,  g_waH);
    cudaGetSymbolAddress((void**)&wqhi, g_wqhi);
    cudaGetSymbolAddress((void**)&wqlo, g_wqlo);
    cudaGetSymbolAddress((void**)&w1H,  g_w1H);
    cudaGetSymbolAddress((void**)&w2H,  g_w2H);

    const int ROWS = BATCH * SEQ;  // 4096

    cudaFuncSetAttribute(gemm_wq, cudaFuncAttributeMaxDynamicSharedMemorySize,
                         WQ_SMEM_BYTES);
    cudaFuncSetAttribute(flash_h, cudaFuncAttributeMaxDynamicSharedMemorySize,
                         FLASH_SMEM_BYTES);
    cudaFuncSetAttribute(gemm_h<1>, cudaFuncAttributeMaxDynamicSharedMemorySize,
                         GH_SMEM_BYTES);
    cudaFuncSetAttribute(gemm_h<2>, cudaFuncAttributeMaxDynamicSharedMemorySize,
                         GH_SMEM_BYTES);
    cudaFuncSetAttribute(gemm_h<3>, cudaFuncAttributeMaxDynamicSharedMemorySize,
                         GH_SMEM_BYTES);

    // 0+1. fused: rmsnorm1+split of x AND weight prep, one launch
    const int prepBlocks = (N_WA + 3 * N_W + 255) / 256;
    prep_kernel<<<ROWS + prepBlocks, 256>>>(
        x, g1, xhi, xlo, WA, W1, W2, Wq, waH, w1H, w2H, wqhi, wqlo);

    // 2. q = (xn @ Wq^T) * coef(head(flat)) -> half hi/lo (compensated fp16)
    gemm_wq<<<dim3(CH / 128, ROWS / 128, 1), 256, WQ_SMEM_BYTES>>>(
        xhi, xlo, wqhi, wqlo, qhi, qlo, scale, ROWS, CH, CH);

    // 3. transpose-gather V' -> vpT[b][c][token]
    tr_gather_kernel<<<dim3(SEQ / 32, HEADS, BATCH), 256>>>(xhi, vpT);

    // 4. vT[b][c][m] = NT(vpT, waH) — premix with direct transposed half output
    gemm_h<3><<<dim3(SEQ / 128, CH / 128, BATCH), 256, GH_SMEM_BYTES>>>(
        vpT, waH, nullptr, vT, nullptr, CH, SEQ, SEQ,
        (long)L_PER_B, 0, (long)L_PER_B);

    // 5. attention (+x residual)
    flash_h<<<dim3(SEQ / 128, HEADS, BATCH), 256, FLASH_SMEM_BYTES>>>(
        qhi, qlo, xhi, xlo, vT, x, res);

    // 6. hh = rmsnorm(res, g2) -> half
    rmsnorm_h_kernel<<<ROWS, 256>>>(res, g2, hh);

    // 7. h1 = gelu(hh @ W1^T) -> half
    gemm_h<1><<<dim3(CH / 128, ROWS / 128, 1), 256, GH_SMEM_BYTES>>>(
        hh, w1H, nullptr, h1, nullptr, ROWS, CH, CH, 0, 0, 0);

    // 8. out = h1 @ W2^T + res
    gemm_h<2><<<dim3(CH / 128, ROWS / 128, 1), 256, GH_SMEM_BYTES>>>(
        h1, w2H, out, nullptr, res, ROWS, CH, CH, 0, 0, 0);
}

// round 17
// speedup vs baseline: 1.1890x; 1.0996x over previous
#include <cuda_runtime.h>
#include <cuda_fp16.h>
#include <math.h>

// ---------------------------------------------------------------------------
// Problem constants
// ---------------------------------------------------------------------------
#define BATCH 2
#define SEQ   2048
#define CH    768
#define HEADS 24
#define HD    32
#define L_PER_B (SEQ * CH)
#define TOT (BATCH * SEQ * CH)

// fp32 scratch
__device__ float g_res[TOT];
// half scratch
__device__ __half g_xhi[TOT];
__device__ __half g_xlo[TOT];
__device__ __half g_qhi[TOT];
__device__ __half g_qlo[TOT];
__device__ __half g_vpT[TOT];     // [b][c][token]
__device__ __half g_vT[TOT];      // [b][c][token]
__device__ __half g_hh[TOT];
__device__ __half g_h1[TOT];
__device__ __half g_waH[SEQ * SEQ];
__device__ __half g_wqhi[CH * CH];
__device__ __half g_wqlo[CH * CH];
__device__ __half g_w1H[CH * CH];
__device__ __half g_w2H[CH * CH];

// ---------------------------------------------------------------------------
// helpers
// ---------------------------------------------------------------------------
__device__ __forceinline__ float gelu_exact(float v)
{
    return 0.5f * v * (1.0f + erff(v * 0.7071067811865476f));
}

__device__ __forceinline__ void h_split(float x, __half& hi, __half& lo)
{
    hi = __float2half_rn(x);
    lo = __float2half_rn(x - __half2float(hi));
}

__device__ __forceinline__ unsigned pack_h2(float a, float b)
{
    __half2 h = __floats2half2_rn(a, b);
    return *(unsigned*)&h;
}

__device__ __forceinline__ void mma_f16(float* c, const unsigned* a, const unsigned* b)
{
    asm volatile(
        "mma.sync.aligned.m16n8k16.row.col.f32.f16.f16.f32 "
        "{%0,%1,%2,%3}, {%4,%5,%6,%7}, {%8,%9}, {%0,%1,%2,%3};"
        : "+f"(c[0]), "+f"(c[1]), "+f"(c[2]), "+f"(c[3])
        : "r"(a[0]), "r"(a[1]), "r"(a[2]), "r"(a[3]), "r"(b[0]), "r"(b[1]));
}

__device__ __forceinline__ unsigned smaddr(const void* p)
{
    return (unsigned)__cvta_generic_to_shared(p);
}

__device__ __forceinline__ void ldsm_x4(unsigned* r, const void* p)
{
    asm volatile("ldmatrix.sync.aligned.m8n8.x4.shared.b16 {%0,%1,%2,%3}, [%4];"
        : "=r"(r[0]), "=r"(r[1]), "=r"(r[2]), "=r"(r[3]) : "r"(smaddr(p)));
}

__device__ __forceinline__ void cp_async16(void* smem, const void* gmem)
{
    asm volatile("cp.async.cg.shared.global [%0], [%1], 16;"
        :: "r"(smaddr(smem)), "l"(gmem));
}
#define CP_COMMIT() asm volatile("cp.async.commit_group;")
#define CP_WAIT0()  asm volatile("cp.async.wait_group 0;")
#define CP_WAIT1()  asm volatile("cp.async.wait_group 1;")

// ---------------------------------------------------------------------------
// RMSNorm reduce helper
// ---------------------------------------------------------------------------
__device__ __forceinline__ float rms_inv(float v0, float v1, float v2, int t)
{
    float ss = v0 * v0 + v1 * v1 + v2 * v2;
    __shared__ float red[8];
    #pragma unroll
    for (int o = 16; o > 0; o >>= 1) ss += __shfl_xor_sync(0xffffffffu, ss, o);
    if ((t & 31) == 0) red[t >> 5] = ss;
    __syncthreads();
    if (t < 8) {
        float s = red[t];
        #pragma unroll
        for (int o = 4; o > 0; o >>= 1) s += __shfl_xor_sync(0xffu, s, o);
        if (t == 0) red[0] = s;
    }
    __syncthreads();
    return rsqrtf(red[0] * (1.0f / 768.0f) + 1.1920928955078125e-07f);
}

// ---------------------------------------------------------------------------
// Fused prep: blocks [0, ROWS) -> rmsnorm1+split of x; blocks >= ROWS ->
// weight conversion (WA/W1/W2 -> half ; Wq -> hi/lo split).
// ---------------------------------------------------------------------------
#define N_WA (SEQ * SEQ / 4)
#define N_W  (CH * CH / 4)
#define ROWS_G (BATCH * SEQ)

__global__ __launch_bounds__(256)
void prep_kernel(const float* __restrict__ x, const float* __restrict__ g1,
                 __half* __restrict__ xhi, __half* __restrict__ xlo,
                 const float* __restrict__ WA, const float* __restrict__ W1,
                 const float* __restrict__ W2, const float* __restrict__ Wq,
                 __half* __restrict__ waH, __half* __restrict__ w1H,
                 __half* __restrict__ w2H,
                 __half* __restrict__ wqhi, __half* __restrict__ wqlo)
{
    const int t = threadIdx.x;
    if (blockIdx.x < ROWS_G) {
        const int row = blockIdx.x;
        const float* xr = x + (long)row * CH;
        float v0 = xr[t], v1 = xr[t + 256], v2 = xr[t + 512];
        const float inv = rms_inv(v0, v1, v2, t);
        __half h, l;
        h_split(v0 * inv * g1[t], h, l);
        xhi[(long)row * CH + t] = h; xlo[(long)row * CH + t] = l;
        h_split(v1 * inv * g1[t + 256], h, l);
        xhi[(long)row * CH + t + 256] = h; xlo[(long)row * CH + t + 256] = l;
        h_split(v2 * inv * g1[t + 512], h, l);
        xhi[(long)row * CH + t + 512] = h; xlo[(long)row * CH + t + 512] = l;
        return;
    }
    long i = (long)(blockIdx.x - ROWS_G) * blockDim.x + t;
    const float* src;
    __half* dst;
    if (i < N_WA) { src = WA; dst = waH; }
    else if ((i -= N_WA) < N_W) { src = W1; dst = w1H; }
    else if ((i -= N_W) < N_W)  { src = W2; dst = w2H; }
    else if ((i -= N_W) < N_W) {
        const long e = i * 4;
        float4 v = *(const float4*)(Wq + e);
        __half h0, l0, h1, l1, h2, l2, h3, l3;
        h_split(v.x, h0, l0); h_split(v.y, h1, l1);
        h_split(v.z, h2, l2); h_split(v.w, h3, l3);
        *(__half2*)(wqhi + e)     = __halves2half2(h0, h1);
        *(__half2*)(wqhi + e + 2) = __halves2half2(h2, h3);
        *(__half2*)(wqlo + e)     = __halves2half2(l0, l1);
        *(__half2*)(wqlo + e + 2) = __halves2half2(l2, l3);
        return;
    } else return;
    const long e = i * 4;
    float4 v = *(const float4*)(src + e);
    *(__half2*)(dst + e)     = __floats2half2_rn(v.x, v.y);
    *(__half2*)(dst + e + 2) = __floats2half2_rn(v.z, v.w);
}

__global__ __launch_bounds__(256)
void rmsnorm_h_kernel(const float* __restrict__ x, const float* __restrict__ g,
                      __half* __restrict__ y)
{
    const int row = blockIdx.x;
    const int t = threadIdx.x;
    const float* xr = x + (long)row * CH;
    float v0 = xr[t], v1 = xr[t + 256], v2 = xr[t + 512];
    const float inv = rms_inv(v0, v1, v2, t);
    __half* yr = y + (long)row * CH;
    yr[t]       = __float2half_rn(v0 * inv * g[t]);
    yr[t + 256] = __float2half_rn(v1 * inv * g[t + 256]);
    yr[t + 512] = __float2half_rn(v2 * inv * g[t + 512]);
}

// ---------------------------------------------------------------------------
// Transpose-gather: xhi (H,N,HD flat view, half) -> vpT[b][c][token]
// ---------------------------------------------------------------------------
__global__ __launch_bounds__(256)
void tr_gather_kernel(const __half* __restrict__ xhi, __half* __restrict__ vpT)
{
    __shared__ __half smt[32][34];
    const int b = blockIdx.z, h = blockIdx.y, m0 = blockIdx.x * 32;
    const int tx = threadIdx.x & 31, ty = threadIdx.x >> 5;
    const __half* src = xhi + (long)b * L_PER_B + (long)h * (SEQ * HD);
    #pragma unroll
    for (int i = 0; i < 4; i++)
        smt[ty + 8 * i][tx] = src[(long)(m0 + ty + 8 * i) * HD + tx];
    __syncthreads();
    __half* dst = vpT + (long)b * L_PER_B;
    #pragma unroll
    for (int i = 0; i < 4; i++) {
        const int d = ty + 8 * i;
        dst[(long)(h * 32 + d) * SEQ + m0 + tx] = smt[tx][d];
    }
}

// ---------------------------------------------------------------------------
// fp16 NT GEMM: C[m][n] = sum_k A[m][k] * B[n][k].
// 64x128 tile, 128 threads (4 warps, each 64x32), ldmatrix, 3-stage pipeline.
// Grid: (N/128, M/64, batch) -> 384 blocks for the block shapes here.
// EPI: 0 -> fp32 C ; 1 -> exact GELU, half Ch ; 2 -> +R, fp32 C ; 3 -> half Ch
// ---------------------------------------------------------------------------
#define GH_A_BUF 2560            // 64 x 40 halfs
#define GH_B_BUF 5120            // 128 x 40 halfs
#define GH_SMEM_BYTES (3 * (GH_A_BUF + GH_B_BUF) * 2)

template<int EPI>
__global__ __launch_bounds__(128)
void gemm_h(const __half* __restrict__ A, const __half* __restrict__ B,
            float* __restrict__ C, __half* __restrict__ Ch,
            const float* __restrict__ R,
            int M, int N, int K, long sA, long sB, long sC)
{
    extern __shared__ __half smh[];
    __half* Asm = smh;
    __half* Bsm = smh + 3 * GH_A_BUF;

    A += (long)blockIdx.z * sA;
    B += (long)blockIdx.z * sB;
    if (EPI == 1 || EPI == 3) Ch += (long)blockIdx.z * sC;
    else                      C  += (long)blockIdx.z * sC;
    if (EPI == 2) R += (long)blockIdx.z * sC;

    const int t = threadIdx.x;
    const int w = t >> 5, lane = t & 31;
    const int g = lane >> 2, tg = lane & 3;
    const int m0 = blockIdx.y * 64, n0 = blockIdx.x * 128;
    const int nk = K >> 5;

    const int jj = lane >> 3, r8 = lane & 7;
    const int aRow = (jj & 1) * 8 + r8, aCol = (jj >> 1) * 8;
    const int bRow = (jj >> 1) * 8 + r8, bCol = (jj & 1) * 8;

    auto stage = [&](int s, int k0) {
        __half* as = Asm + s * GH_A_BUF;
        __half* bs = Bsm + s * GH_B_BUF;
        #pragma unroll
        for (int i = 0; i < 2; i++) {          // A: 64 rows, 256 chunks
            const int f = t + i * 128;
            const int row = f >> 2, seg = f & 3;
            cp_async16(&as[row * 40 + seg * 8], A + (long)(m0 + row) * K + k0 + seg * 8);
        }
        #pragma unroll
        for (int i = 0; i < 4; i++) {          // B: 128 rows, 512 chunks
            const int f = t + i * 128;
            const int row = f >> 2, seg = f & 3;
            cp_async16(&bs[row * 40 + seg * 8], B + (long)(n0 + row) * K + k0 + seg * 8);
        }
    };

    float acc[4][4][4] = {};

    stage(0, 0);
    CP_COMMIT();
    if (nk > 1) { stage(1, 32); CP_COMMIT(); }

    int sb = 0;
    for (int kt = 0; kt < nk; kt++) {
        if (kt + 1 < nk) { CP_WAIT1(); } else { CP_WAIT0(); }
        __syncthreads();
        if (kt + 2 < nk) {
            stage((sb + 2) % 3, (kt + 2) * 32);
            CP_COMMIT();
        }

        const __half* as = Asm + sb * GH_A_BUF;
        const __half* bs = Bsm + sb * GH_B_BUF;

        #pragma unroll
        for (int kc = 0; kc < 2; kc++) {
            const int kb = kc * 16;
            unsigned a[4][4], b2[2][4];
            #pragma unroll
            for (int mt = 0; mt < 4; mt++)
                ldsm_x4(a[mt], &as[(mt * 16 + aRow) * 40 + kb + aCol]);
            #pragma unroll
            for (int np = 0; np < 2; np++)
                ldsm_x4(b2[np], &bs[(w * 32 + np * 16 + bRow) * 40 + kb + bCol]);
            #pragma unroll
            for (int mt = 0; mt < 4; mt++)
                #pragma unroll
                for (int nt = 0; nt < 4; nt++)
                    mma_f16(acc[mt][nt], a[mt], &b2[nt >> 1][(nt & 1) * 2]);
        }
        sb = (sb + 1) % 3;
    }

    #pragma unroll
    for (int mt = 0; mt < 4; mt++) {
        #pragma unroll
        for (int nt = 0; nt < 4; nt++) {
            const int row0 = m0 + mt * 16 + g;
            const int col  = n0 + w * 32 + nt * 8 + 2 * tg;
            float v0 = acc[mt][nt][0], v1 = acc[mt][nt][1];
            float v2 = acc[mt][nt][2], v3 = acc[mt][nt][3];
            if (EPI == 1 || EPI == 3) {
                if (EPI == 1) {
                    v0 = gelu_exact(v0); v1 = gelu_exact(v1);
                    v2 = gelu_exact(v2); v3 = gelu_exact(v3);
                }
                *(__half2*)(Ch + (long)row0 * N + col) = __floats2half2_rn(v0, v1);
                *(__half2*)(Ch + (long)(row0 + 8) * N + col) = __floats2half2_rn(v2, v3);
            } else {
                if (EPI == 2) {
                    float2 r0 = *(const float2*)(R + (long)row0 * N + col);
                    float2 r1 = *(const float2*)(R + (long)(row0 + 8) * N + col);
                    v0 += r0.x; v1 += r0.y; v2 += r1.x; v3 += r1.y;
                }
                float2 o0 = {v0, v1}, o1 = {v2, v3};
                *(float2*)(C + (long)row0 * N + col) = o0;
                *(float2*)(C + (long)(row0 + 8) * N + col) = o1;
            }
        }
    }
}

// ---------------------------------------------------------------------------
// Wq projection: compensated fp16 NT GEMM, pre-split operands, ldmatrix.
// 64x128 tile, 128 threads, 2-stage prefetch-before-wait pipeline.
// ---------------------------------------------------------------------------
#define WQ_SMEM_BYTES (2 * (2 * GH_A_BUF + 2 * GH_B_BUF) * 2)

__global__ __launch_bounds__(128)
void gemm_wq(const __half* __restrict__ Ahi, const __half* __restrict__ Alo,
             const __half* __restrict__ Bhi, const __half* __restrict__ Blo,
             __half* __restrict__ Chi, __half* __restrict__ Clo,
             const float* __restrict__ scale_param, int M, int N, int K)
{
    extern __shared__ __half smw[];
    __half* AH = smw;                            // 2 x 2560
    __half* AL = smw + 2 * GH_A_BUF;             // 2 x 2560
    __half* BH = smw + 4 * GH_A_BUF;             // 2 x 5120
    __half* BL = smw + 4 * GH_A_BUF + 2 * GH_B_BUF;
    __shared__ float scoef[HEADS];

    const int t = threadIdx.x;
    if (t < HEADS)
        scoef[t] = logf(768.0f) * scale_param[t] * 5.656854249492381f;

    const int w = t >> 5, lane = t & 31;
    const int g = lane >> 2, tg = lane & 3;
    const int m0 = blockIdx.y * 64, n0 = blockIdx.x * 128;
    const int nk = K >> 5;

    const int jj = lane >> 3, r8 = lane & 7;
    const int aRow = (jj & 1) * 8 + r8, aCol = (jj >> 1) * 8;
    const int bRow = (jj >> 1) * 8 + r8, bCol = (jj & 1) * 8;

    auto stage = [&](int s, int k0) {
        __half* ah = AH + s * GH_A_BUF;
        __half* al = AL + s * GH_A_BUF;
        __half* bh = BH + s * GH_B_BUF;
        __half* bl = BL + s * GH_B_BUF;
        #pragma unroll
        for (int i = 0; i < 2; i++) {
            const int f = t + i * 128;
            const int row = f >> 2, seg = f & 3;
            const long src = (long)(m0 + row) * K + k0 + seg * 8;
            cp_async16(&ah[row * 40 + seg * 8], Ahi + src);
            cp_async16(&al[row * 40 + seg * 8], Alo + src);
        }
        #pragma unroll
        for (int i = 0; i < 4; i++) {
            const int f = t + i * 128;
            const int row = f >> 2, seg = f & 3;
            const long src = (long)(n0 + row) * K + k0 + seg * 8;
            cp_async16(&bh[row * 40 + seg * 8], Bhi + src);
            cp_async16(&bl[row * 40 + seg * 8], Blo + src);
        }
    };

    float acc[4][4][4] = {};

    stage(0, 0);
    CP_COMMIT();

    for (int kt = 0; kt < nk; kt++) {
        if (kt + 1 < nk) {
            stage((kt + 1) & 1, (kt + 1) * 32);
            CP_COMMIT();
            CP_WAIT1();
        } else {
            CP_WAIT0();
        }
        __syncthreads();

        const __half* ah = AH + (kt & 1) * GH_A_BUF;
        const __half* al = AL + (kt & 1) * GH_A_BUF;
        const __half* bh = BH + (kt & 1) * GH_B_BUF;
        const __half* bl = BL + (kt & 1) * GH_B_BUF;

        #pragma unroll
        for (int kc = 0; kc < 2; kc++) {
            const int kb = kc * 16;
            unsigned aH[4][4], aL[4][4], bH2[2][4], bL2[2][4];
            #pragma unroll
            for (int mt = 0; mt < 4; mt++) {
                const int ao = (mt * 16 + aRow) * 40 + kb + aCol;
                ldsm_x4(aH[mt], &ah[ao]);
                ldsm_x4(aL[mt], &al[ao]);
            }
            #pragma unroll
            for (int np = 0; np < 2; np++) {
                const int bo = (w * 32 + np * 16 + bRow) * 40 + kb + bCol;
                ldsm_x4(bH2[np], &bh[bo]);
                ldsm_x4(bL2[np], &bl[bo]);
            }
            #pragma unroll
            for (int mt = 0; mt < 4; mt++)
                #pragma unroll
                for (int nt = 0; nt < 4; nt++) {
                    const unsigned* pbh = &bH2[nt >> 1][(nt & 1) * 2];
                    const unsigned* pbl = &bL2[nt >> 1][(nt & 1) * 2];
                    mma_f16(acc[mt][nt], aH[mt], pbh);
                    mma_f16(acc[mt][nt], aH[mt], pbl);
                    mma_f16(acc[mt][nt], aL[mt], pbh);
                }
        }
        __syncthreads();
    }

    #pragma unroll
    for (int mt = 0; mt < 4; mt++) {
        #pragma unroll
        for (int nt = 0; nt < 4; nt++) {
            const int row0 = m0 + mt * 16 + g;
            const int col  = n0 + w * 32 + nt * 8 + 2 * tg;
            const int n0b = row0 & (SEQ - 1);
            const int f00 = n0b * CH + col;
            const int f10 = (n0b + 8) * CH + col;
            const float c00 = scoef[f00 >> 16];
            const float c01 = scoef[(f00 + 1) >> 16];
            const float c10 = scoef[f10 >> 16];
            const float c11 = scoef[(f10 + 1) >> 16];
            float v0 = acc[mt][nt][0] * c00, v1 = acc[mt][nt][1] * c01;
            float v2 = acc[mt][nt][2] * c10, v3 = acc[mt][nt][3] * c11;
            __half h0, l0, h1, l1, h2, l2, h3, l3;
            h_split(v0, h0, l0); h_split(v1, h1, l1);
            h_split(v2, h2, l2); h_split(v3, h3, l3);
            *(__half2*)(Chi + (long)row0 * N + col) = __halves2half2(h0, h1);
            *(__half2*)(Clo + (long)row0 * N + col) = __halves2half2(l0, l1);
            *(__half2*)(Chi + (long)(row0 + 8) * N + col) = __halves2half2(h2, h3);
            *(__half2*)(Clo + (long)(row0 + 8) * N + col) = __halves2half2(l2, l3);
        }
    }
}

// ---------------------------------------------------------------------------
// fp16 flash attention, ldmatrix frags, 2-stage prefetch-before-wait.
// QK: hi/lo 3-term fp16. PV: single fp16. (unchanged from best config)
// ---------------------------------------------------------------------------
#define FK_HI(s) ((s) * 2560)
#define FK_LO(s) (5120 + (s) * 2560)
#define FV(s)    (10240 + (s) * 2304)
#define FLASH_SMEM_BYTES (14848 * 2)

__global__ __launch_bounds__(256, 2)
void flash_h(const __half* __restrict__ Qhi, const __half* __restrict__ Qlo,
             const __half* __restrict__ Khi, const __half* __restrict__ Klo,
             const __half* __restrict__ VT,
             const float* __restrict__ X, float* __restrict__ O)
{
    extern __shared__ __half smf[];

    const int b = blockIdx.z, h = blockIdx.y;
    const int t = threadIdx.x, w = t >> 5, lane = t & 31;
    const int g = lane >> 2, tg = lane & 3;
    const long baseqk = (long)b * L_PER_B + (long)h * (SEQ * HD);
    const long basevT = (long)b * L_PER_B + (long)(h * HD) * SEQ;

    const int row0 = blockIdx.x * 128 + w * 16 + g;

    const int jj = lane >> 3, r8 = lane & 7;
    const int bRow = (jj >> 1) * 8 + r8, bCol = (jj & 1) * 8;

    auto stage = [&](int s, int kt) {
        __half* kh = smf + FK_HI(s);
        __half* kl = smf + FK_LO(s);
        __half* vh = smf + FV(s);
        {
            const int row = t >> 2, seg = t & 3;
            const long src = baseqk + (long)(kt * 64 + row) * HD + seg * 8;
            cp_async16(&kh[row * 40 + seg * 8], Khi + src);
            cp_async16(&kl[row * 40 + seg * 8], Klo + src);
        }
        {
            const int d = t >> 3, seg = t & 7;
            const long src = basevT + (long)d * SEQ + kt * 64 + seg * 8;
            cp_async16(&vh[d * 72 + seg * 8], VT + src);
        }
    };

    unsigned qh[2][4], ql[2][4];
    #pragma unroll
    for (int kc = 0; kc < 2; kc++) {
        #pragma unroll
        for (int rr = 0; rr < 2; rr++) {
            const long base = baseqk + (long)(row0 + rr * 8) * HD + kc * 16 + 2 * tg;
            qh[kc][rr]     = *(const unsigned*)&Qhi[base];
            qh[kc][rr + 2] = *(const unsigned*)&Qhi[base + 8];
            ql[kc][rr]     = *(const unsigned*)&Qlo[base];
            ql[kc][rr + 2] = *(const unsigned*)&Qlo[base + 8];
        }
    }

    float acco[4][4] = {};
    float Mx[2] = {-1e30f, -1e30f};
    float Srun[2] = {0.0f, 0.0f};
    const unsigned full = 0xffffffffu;

    stage(0, 0);
    CP_COMMIT();

    for (int kt = 0; kt < SEQ / 64; kt++) {
        if (kt + 1 < SEQ / 64) {
            stage((kt + 1) & 1, kt + 1);
            CP_COMMIT();
            CP_WAIT1();
        } else {
            CP_WAIT0();
        }
        __syncthreads();

        const int s = kt & 1;
        const __half* ksh_hi = smf + FK_HI(s);
        const __half* ksh_lo = smf + FK_LO(s);
        const __half* vsh = smf + FV(s);

        // ---- S = Q K^T (ldmatrix K-frags) ----
        float accs[8][4] = {};
        #pragma unroll
        for (int kc = 0; kc < 2; kc++) {
            const int kb = kc * 16;
            #pragma unroll
            for (int np = 0; np < 4; np++) {
                unsigned bh4[4], bl4[4];
                const int ko = (np * 16 + bRow) * 40 + kb + bCol;
                ldsm_x4(bh4, &ksh_hi[ko]);
                ldsm_x4(bl4, &ksh_lo[ko]);
                #pragma unroll
                for (int q = 0; q < 2; q++) {
                    const int nt = np * 2 + q;
                    mma_f16(accs[nt], qh[kc], &bh4[q * 2]);
                    mma_f16(accs[nt], qh[kc], &bl4[q * 2]);
                    mma_f16(accs[nt], ql[kc], &bh4[q * 2]);
                }
            }
        }

        // ---- online softmax ----
        #pragma unroll
        for (int rr = 0; rr < 2; rr++) {
            const int i0 = rr * 2, i1 = rr * 2 + 1;
            float m = accs[0][i0];
            #pragma unroll
            for (int nt = 0; nt < 8; nt++) {
                m = fmaxf(m, accs[nt][i0]);
                m = fmaxf(m, accs[nt][i1]);
            }
            m = fmaxf(m, __shfl_xor_sync(full, m, 1));
            m = fmaxf(m, __shfl_xor_sync(full, m, 2));
            const float Mn = fmaxf(Mx[rr], m);
            const float corr = __expf(Mx[rr] - Mn);
            Srun[rr] *= corr;
            #pragma unroll
            for (int nt = 0; nt < 4; nt++) {
                acco[nt][i0] *= corr;
                acco[nt][i1] *= corr;
            }
            Mx[rr] = Mn;
            float lsum = 0.0f;
            #pragma unroll
            for (int nt = 0; nt < 8; nt++) {
                const float p0 = __expf(accs[nt][i0] - Mn);
                const float p1 = __expf(accs[nt][i1] - Mn);
                lsum += p0 + p1;
                accs[nt][i0] = p0;
                accs[nt][i1] = p1;
            }
            lsum += __shfl_xor_sync(full, lsum, 1);
            lsum += __shfl_xor_sync(full, lsum, 2);
            Srun[rr] += lsum;
        }

        // ---- pack P to fp16 A-fragments ----
        unsigned ph[8][2];
        #pragma unroll
        for (int nt = 0; nt < 8; nt++) {
            ph[nt][0] = pack_h2(accs[nt][0], accs[nt][1]);
            ph[nt][1] = pack_h2(accs[nt][2], accs[nt][3]);
        }

        // ---- O += P V (ldmatrix V-frags) ----
        #pragma unroll
        for (int kcK = 0; kcK < 4; kcK++) {
            unsigned pa[4] = {ph[2 * kcK][0], ph[2 * kcK][1],
                              ph[2 * kcK + 1][0], ph[2 * kcK + 1][1]};
            #pragma unroll
            for (int vp = 0; vp < 2; vp++) {
                unsigned v4[4];
                ldsm_x4(v4, &vsh[(vp * 16 + bRow) * 72 + kcK * 16 + bCol]);
                mma_f16(acco[vp * 2],     pa, &v4[0]);
                mma_f16(acco[vp * 2 + 1], pa, &v4[2]);
            }
        }
        __syncthreads();
    }

    // ---- epilogue: /S, +x, store ----
    const float inv0 = 1.0f / Srun[0];
    const float inv1 = 1.0f / Srun[1];
    #pragma unroll
    for (int nt = 0; nt < 4; nt++) {
        const int col = nt * 8 + 2 * tg;
        const long a0 = baseqk + (long)row0 * HD + col;
        const long a1 = baseqk + (long)(row0 + 8) * HD + col;
        float2 x0 = *(const float2*)(X + a0);
        float2 x1 = *(const float2*)(X + a1);
        float2 o0 = {acco[nt][0] * inv0 + x0.x, acco[nt][1] * inv0 + x0.y};
        float2 o1 = {acco[nt][2] * inv1 + x1.x, acco[nt][3] * inv1 + x1.y};
        *(float2*)(O + a0) = o0;
        *(float2*)(O + a1) = o1;
    }
}

// ---------------------------------------------------------------------------
// Launch
// ---------------------------------------------------------------------------
extern "C" void kernel_launch(void* const* d_in, const int* in_sizes, int n_in,
                              void* d_out, int out_size)
{
    const float* x     = (const float*)d_in[0];
    const float* scale = (const float*)d_in[1];
    const float* Wq    = (const float*)d_in[2];
    const float* WA    = (const float*)d_in[3];
    const float* W1    = (const float*)d_in[4];
    const float* W2    = (const float*)d_in[5];
    const float* g1    = (const float*)d_in[6];
    const float* g2    = (const float*)d_in[7];
    float* out = (float*)d_out;

    float *res;
    __half *xhi, *xlo, *qhi, *qlo, *vpT, *vT, *hh, *h1;
    __half *waH, *wqhi, *wqlo, *w1H, *w2H;
    cudaGetSymbolAddress((void**)&res,  g_res);
    cudaGetSymbolAddress((void**)&xhi,  g_xhi);
    cudaGetSymbolAddress((void**)&xlo,  g_xlo);
    cudaGetSymbolAddress((void**)&qhi,  g_qhi);
    cudaGetSymbolAddress((void**)&qlo,  g_qlo);
    cudaGetSymbolAddress((void**)&vpT,  g_vpT);
    cudaGetSymbolAddress((void**)&vT,   g_vT);
    cudaGetSymbolAddress((void**)&hh,   g_hh);
    cudaGetSymbolAddress((void**)&h1,   g_h1);
    cudaGetSymbolAddress((void**)&waH,  g_waH);
    cudaGetSymbolAddress((void**)&wqhi, g_wqhi);
    cudaGetSymbolAddress((void**)&wqlo, g_wqlo);
    cudaGetSymbolAddress((void**)&w1H,  g_w1H);
    cudaGetSymbolAddress((void**)&w2H,  g_w2H);

    const int ROWS = BATCH * SEQ;  // 4096

    cudaFuncSetAttribute(gemm_wq, cudaFuncAttributeMaxDynamicSharedMemorySize,
                         WQ_SMEM_BYTES);
    cudaFuncSetAttribute(flash_h, cudaFuncAttributeMaxDynamicSharedMemorySize,
                         FLASH_SMEM_BYTES);
    cudaFuncSetAttribute(gemm_h<1>, cudaFuncAttributeMaxDynamicSharedMemorySize,
                         GH_SMEM_BYTES);
    cudaFuncSetAttribute(gemm_h<2>, cudaFuncAttributeMaxDynamicSharedMemorySize,
                         GH_SMEM_BYTES);
    cudaFuncSetAttribute(gemm_h<3>, cudaFuncAttributeMaxDynamicSharedMemorySize,
                         GH_SMEM_BYTES);

    // 0+1. fused: rmsnorm1+split of x AND weight prep, one launch
    const int prepBlocks = (N_WA + 3 * N_W + 255) / 256;
    prep_kernel<<<ROWS + prepBlocks, 256>>>(
        x, g1, xhi, xlo, WA, W1, W2, Wq, waH, w1H, w2H, wqhi, wqlo);

    // 2. q = (xn @ Wq^T) * coef(head(flat)) -> half hi/lo (compensated fp16)
    gemm_wq<<<dim3(CH / 128, ROWS / 64, 1), 128, WQ_SMEM_BYTES>>>(
        xhi, xlo, wqhi, wqlo, qhi, qlo, scale, ROWS, CH, CH);

    // 3. transpose-gather V' -> vpT[b][c][token]
    tr_gather_kernel<<<dim3(SEQ / 32, HEADS, BATCH), 256>>>(xhi, vpT);

    // 4. vT[b][c][m] = NT(vpT, waH) — premix with direct transposed half output
    gemm_h<3><<<dim3(SEQ / 128, CH / 64, BATCH), 128, GH_SMEM_BYTES>>>(
        vpT, waH, nullptr, vT, nullptr, CH, SEQ, SEQ,
        (long)L_PER_B, 0, (long)L_PER_B);

    // 5. attention (+x residual)
    flash_h<<<dim3(SEQ / 128, HEADS, BATCH), 256, FLASH_SMEM_BYTES>>>(
        qhi, qlo, xhi, xlo, vT, x, res);

    // 6. hh = rmsnorm(res, g2) -> half
    rmsnorm_h_kernel<<<ROWS, 256>>>(res, g2, hh);

    // 7. h1 = gelu(hh @ W1^T) -> half
    gemm_h<1><<<dim3(CH / 128, ROWS / 64, 1), 128, GH_SMEM_BYTES>>>(
        hh, w1H, nullptr, h1, nullptr, ROWS, CH, CH, 0, 0, 0);

    // 8. out = h1 @ W2^T + res
    gemm_h<2><<<dim3(CH / 128, ROWS / 64, 1), 128, GH_SMEM_BYTES>>>(
        h1, w2H, out, nullptr, res, ROWS, CH, CH, 0, 0, 0);
}